// round 4
// baseline (speedup 1.0000x reference)
#include <cuda_runtime.h>

// Problem constants (fixed by setup_inputs)
#define T_LEN    131072
#define K_WIN    31
#define HALO     15            // (K-1)/2
#define TILE     2048          // elements per block; T_LEN / TILE = 64 exactly
#define NTHREADS 128
#define CHUNK    16            // elements per thread
#define GROUP    8             // MLP batch per thread (4 packed pairs)
#define LPITCH   (TILE + 8)    // padded plane pitch for logits staging
#define HIDDEN   32
#define INFEATS  6
#define EPS      1e-6f
#define KURT_MAX 20.0f

typedef unsigned long long ull;

// ---- packed fp32x2 helpers (Blackwell sm_100a) ------------------------------
__device__ __forceinline__ ull pack2(float lo, float hi) {
    ull r; asm("mov.b64 %0, {%1, %2};" : "=l"(r) : "f"(lo), "f"(hi)); return r;
}
__device__ __forceinline__ void unpack2(ull a, float &lo, float &hi) {
    asm("mov.b64 {%0, %1}, %2;" : "=f"(lo), "=f"(hi) : "l"(a));
}
__device__ __forceinline__ ull fma2(ull a, ull b, ull c) {
    ull d; asm("fma.rn.f32x2 %0, %1, %2, %3;" : "=l"(d) : "l"(a), "l"(b), "l"(c));
    return d;
}
__device__ __forceinline__ ull relu2(ull a) {
    float lo, hi; unpack2(a, lo, hi);
    return pack2(fmaxf(lo, 0.0f), fmaxf(hi, 0.0f));
}

// Compute the 6 features for one element and advance the sliding sums.
// idx: position of (t - 15) within xs. t: global time index (for d2 edge zeroing).
__device__ __forceinline__ void feat_step(
    const float* __restrict__ xs, int idx, int t,
    float &S1, float &S2, float &S3, float &S4,
    float &f0, float &f1, float &f2, float &f3, float &f4, float &f5)
{
    const float INV31 = 1.0f / 31.0f;
    float mu = S1 * INV31;
    float m2 = S2 * INV31;
    float m3 = S3 * INV31;
    float m4 = S4 * INV31;
    float mu2 = mu * mu;
    float var = m2 - mu2 + EPS;
    float m4c = m4 - 4.0f * mu * m3 + 6.0f * mu2 * m2 - 3.0f * mu2 * mu2;
    float kurt = fminf(m4c / (var * var), KURT_MAX);

    float x  = xs[idx + 15];
    float xm = xs[idx + 14];
    float xp = xs[idx + 16];
    float d1 = fabsf(x - xm);                 // clamp-load makes d1[0] == 0 naturally
    float d2 = fabsf(xp - 2.0f * x + xm);
    if (t == 0 || t == T_LEN - 1) d2 = 0.0f;  // zero-pad edges of 2nd diff

    f0 = x; f1 = d1; f2 = d2; f3 = mu; f4 = var; f5 = kurt;

    // slide window: t -> t+1 adds xs[idx+31], drops xs[idx]
    float xa = xs[idx + 31];
    float xr = xs[idx];
    float xa2 = xa * xa, xr2 = xr * xr;
    S1 += xa - xr;
    S2 += xa2 - xr2;
    S3 += xa2 * xa - xr2 * xr;
    S4 += xa2 * xa2 - xr2 * xr2;
}

__global__ __launch_bounds__(NTHREADS, 3)
void gate_router_kernel(const float* __restrict__ s,
                        const float* __restrict__ W1, const float* __restrict__ b1,
                        const float* __restrict__ W2, const float* __restrict__ b2,
                        float* __restrict__ out)
{
    // xs gets 2 extra slots: the (discarded) slide-update after the last element
    // of a thread reads one past the live halo; keep it in-bounds.
    __shared__ float xs[TILE + 2 * HALO + 2];
    __shared__ float lbuf[3 * LPITCH];
    __shared__ ull w1t[HIDDEN * INFEATS];   // [j][i], duplicated (w,w)
    __shared__ ull b1p[HIDDEN];
    __shared__ ull w2p[HIDDEN * 3];         // [j][k], duplicated
    __shared__ ull b2p[3];

    const int tid = threadIdx.x;
    const int tileStart = blockIdx.x * TILE;
    const int row = blockIdx.y;
    const float* __restrict__ srow = s + (long long)row * T_LEN;

    // ---- stage signal tile + halo (index clamp == replicate padding) -------
    for (int i = tid; i < TILE + 2 * HALO + 2; i += NTHREADS) {
        int g = tileStart - HALO + i;
        g = max(0, min(T_LEN - 1, g));
        xs[i] = srow[g];
    }
    // ---- stage duplicated weights as 64-bit (w,w) for f32x2 FMAs -----------
    for (int i = tid; i < HIDDEN * INFEATS; i += NTHREADS) {
        int j = i / INFEATS, f = i - j * INFEATS;
        float w = W1[f * HIDDEN + j];       // transpose: row-per-hidden
        w1t[i] = pack2(w, w);
    }
    if (tid < HIDDEN) { float v = b1[tid]; b1p[tid] = pack2(v, v); }
    for (int i = tid; i < HIDDEN * 3; i += NTHREADS) { float v = W2[i]; w2p[i] = pack2(v, v); }
    if (tid < 3) { float v = b2[tid]; b2p[tid] = pack2(v, v); }
    __syncthreads();

    // ---- init sliding sums for this thread's first element -----------------
    const int base = tid * CHUNK;           // xs index of (t0 - 15)
    float S1 = 0.f, S2 = 0.f, S3 = 0.f, S4 = 0.f;
    #pragma unroll
    for (int k = 0; k < K_WIN; ++k) {
        float v = xs[base + k];
        float v2 = v * v;
        S1 += v; S2 += v2; S3 += v2 * v; S4 += v2 * v2;
    }
    const int t0 = tileStart + base;

    // ---- two groups of 8 elements (4 f32x2 pairs each) ---------------------
    #pragma unroll
    for (int g = 0; g < 2; ++g) {
        ull fp0[4], fp1[4], fp2[4], fp3[4], fp4[4], fp5[4];
        #pragma unroll
        for (int pr = 0; pr < 4; ++pr) {
            int j0 = g * GROUP + pr * 2;
            float a0, a1, a2, a3, a4, a5;
            float c0, c1, c2, c3, c4, c5;
            feat_step(xs, base + j0,     t0 + j0,     S1, S2, S3, S4, a0, a1, a2, a3, a4, a5);
            feat_step(xs, base + j0 + 1, t0 + j0 + 1, S1, S2, S3, S4, c0, c1, c2, c3, c4, c5);
            fp0[pr] = pack2(a0, c0);
            fp1[pr] = pack2(a1, c1);
            fp2[pr] = pack2(a2, c2);
            fp3[pr] = pack2(a3, c3);
            fp4[pr] = pack2(a4, c4);
            fp5[pr] = pack2(a5, c5);
        }

        ull acc0[4], acc1[4], acc2[4];
        #pragma unroll
        for (int pr = 0; pr < 4; ++pr) {
            acc0[pr] = b2p[0]; acc1[pr] = b2p[1]; acc2[pr] = b2p[2];
        }

        #pragma unroll 4
        for (int j = 0; j < HIDDEN; ++j) {
            ull w0 = w1t[j * 6 + 0], w1v = w1t[j * 6 + 1], w2v = w1t[j * 6 + 2];
            ull w3 = w1t[j * 6 + 3], w4v = w1t[j * 6 + 4], w5v = w1t[j * 6 + 5];
            ull bj = b1p[j];
            ull v0 = w2p[j * 3 + 0], v1 = w2p[j * 3 + 1], v2 = w2p[j * 3 + 2];
            #pragma unroll
            for (int pr = 0; pr < 4; ++pr) {
                ull h = fma2(fp0[pr], w0, bj);
                h = fma2(fp1[pr], w1v, h);
                h = fma2(fp2[pr], w2v, h);
                h = fma2(fp3[pr], w3, h);
                h = fma2(fp4[pr], w4v, h);
                h = fma2(fp5[pr], w5v, h);
                h = relu2(h);
                acc0[pr] = fma2(h, v0, acc0[pr]);
                acc1[pr] = fma2(h, v1, acc1[pr]);
                acc2[pr] = fma2(h, v2, acc2[pr]);
            }
        }

        // stash logits in padded planes for coalesced writeout
        #pragma unroll
        for (int pr = 0; pr < 4; ++pr) {
            int e = base + g * GROUP + pr * 2;
            float lo, hi;
            unpack2(acc0[pr], lo, hi); lbuf[0 * LPITCH + e] = lo; lbuf[0 * LPITCH + e + 1] = hi;
            unpack2(acc1[pr], lo, hi); lbuf[1 * LPITCH + e] = lo; lbuf[1 * LPITCH + e + 1] = hi;
            unpack2(acc2[pr], lo, hi); lbuf[2 * LPITCH + e] = lo; lbuf[2 * LPITCH + e + 1] = hi;
        }
    }
    __syncthreads();

    // ---- coalesced float4 writeout: out[(row*T + t)*3 + k] -----------------
    float* __restrict__ orow = out + ((long long)row * T_LEN + tileStart) * 3;
    for (int v = tid; v < (TILE * 3) / 4; v += NTHREADS) {
        int i = 4 * v;
        float4 o;
        o.x = lbuf[((i    ) % 3) * LPITCH + (i    ) / 3];
        o.y = lbuf[((i + 1) % 3) * LPITCH + (i + 1) / 3];
        o.z = lbuf[((i + 2) % 3) * LPITCH + (i + 2) / 3];
        o.w = lbuf[((i + 3) % 3) * LPITCH + (i + 3) / 3];
        reinterpret_cast<float4*>(orow)[v] = o;
    }
}

extern "C" void kernel_launch(void* const* d_in, const int* in_sizes, int n_in,
                              void* d_out, int out_size)
{
    const float* s  = (const float*)d_in[0];   // [B*T]
    const float* W1 = (const float*)d_in[1];   // [6*32]
    const float* b1 = (const float*)d_in[2];   // [32]
    const float* W2 = (const float*)d_in[3];   // [32*3]
    const float* b2 = (const float*)d_in[4];   // [3]
    float* out = (float*)d_out;                // [B*T*3]

    int B = in_sizes[0] / T_LEN;
    dim3 grid(T_LEN / TILE, B);
    gate_router_kernel<<<grid, NTHREADS>>>(s, W1, b1, W2, b2, out);
}

// round 5
// speedup vs baseline: 1.2900x; 1.2900x over previous
#include <cuda_runtime.h>

// Problem constants (fixed by setup_inputs)
#define T_LEN    131072
#define K_WIN    31
#define HALO     15            // (K-1)/2
#define TILE     2048          // elements per block; T_LEN / TILE = 64 exactly
#define NTHREADS 128
#define CHUNK    16            // elements per thread
#define GROUP    8             // MLP batch per thread (4 packed pairs)
#define HIDDEN   32
#define INFEATS  6
#define EPS      1e-6f
#define KURT_MAX 20.0f

typedef unsigned long long ull;

// ---- packed fp32x2 helpers (Blackwell sm_100a) ------------------------------
__device__ __forceinline__ ull pack2(float lo, float hi) {
    ull r; asm("mov.b64 %0, {%1, %2};" : "=l"(r) : "f"(lo), "f"(hi)); return r;
}
__device__ __forceinline__ void unpack2(ull a, float &lo, float &hi) {
    asm("mov.b64 {%0, %1}, %2;" : "=f"(lo), "=f"(hi) : "l"(a));
}
__device__ __forceinline__ ull fma2(ull a, ull b, ull c) {
    ull d; asm("fma.rn.f32x2 %0, %1, %2, %3;" : "=l"(d) : "l"(a), "l"(b), "l"(c));
    return d;
}
__device__ __forceinline__ ull relu2(ull a) {
    float lo, hi; unpack2(a, lo, hi);
    return pack2(fmaxf(lo, 0.0f), fmaxf(hi, 0.0f));
}

// Compute the 6 features for one element and advance the sliding sums.
// idx: position of (t - 15) within xs. t: global time index (for d2 edge zeroing).
__device__ __forceinline__ void feat_step(
    const float* __restrict__ xs, int idx, int t,
    float &S1, float &S2, float &S3, float &S4,
    float &f0, float &f1, float &f2, float &f3, float &f4, float &f5)
{
    const float INV31 = 1.0f / 31.0f;
    float mu = S1 * INV31;
    float m2 = S2 * INV31;
    float m3 = S3 * INV31;
    float m4 = S4 * INV31;
    float mu2 = mu * mu;
    float var = m2 - mu2 + EPS;
    float m4c = m4 - 4.0f * mu * m3 + 6.0f * mu2 * m2 - 3.0f * mu2 * mu2;
    float kurt = fminf(__fdividef(m4c, var * var), KURT_MAX);

    float x  = xs[idx + 15];
    float xm = xs[idx + 14];
    float xp = xs[idx + 16];
    float d1 = fabsf(x - xm);                 // clamp-load makes d1[0] == 0 naturally
    float d2 = fabsf(xp - 2.0f * x + xm);
    if (t == 0 || t == T_LEN - 1) d2 = 0.0f;  // zero-pad edges of 2nd diff

    f0 = x; f1 = d1; f2 = d2; f3 = mu; f4 = var; f5 = kurt;

    // slide window: t -> t+1 adds xs[idx+31], drops xs[idx]
    float xa = xs[idx + 31];
    float xr = xs[idx];
    float xa2 = xa * xa, xr2 = xr * xr;
    S1 += xa - xr;
    S2 += xa2 - xr2;
    S3 += xa2 * xa - xr2 * xr;
    S4 += xa2 * xa2 - xr2 * xr2;
}

__global__ __launch_bounds__(NTHREADS, 4)
void gate_router_kernel(const float* __restrict__ s,
                        const float* __restrict__ W1, const float* __restrict__ b1,
                        const float* __restrict__ W2, const float* __restrict__ b2,
                        float* __restrict__ out)
{
    // xs gets 2 extra slots: the (discarded) slide-update after the last element
    // of a thread reads one past the live halo; keep it in-bounds.
    __shared__ float xs[TILE + 2 * HALO + 2];
    __shared__ ull w1t[HIDDEN * INFEATS];   // [j][i], duplicated (w,w)
    __shared__ ull b1p[HIDDEN];
    __shared__ ull w2p[HIDDEN * 3];         // [j][k], duplicated
    __shared__ ull b2p[3];

    const int tid = threadIdx.x;
    const int tileStart = blockIdx.x * TILE;
    const int row = blockIdx.y;
    const float* __restrict__ srow = s + (long long)row * T_LEN;

    // ---- stage signal tile + halo (index clamp == replicate padding) -------
    for (int i = tid; i < TILE + 2 * HALO + 2; i += NTHREADS) {
        int g = tileStart - HALO + i;
        g = max(0, min(T_LEN - 1, g));
        xs[i] = srow[g];
    }
    // ---- stage duplicated weights as 64-bit (w,w) for f32x2 FMAs -----------
    for (int i = tid; i < HIDDEN * INFEATS; i += NTHREADS) {
        int j = i / INFEATS, f = i - j * INFEATS;
        float w = W1[f * HIDDEN + j];       // transpose: row-per-hidden
        w1t[i] = pack2(w, w);
    }
    if (tid < HIDDEN) { float v = b1[tid]; b1p[tid] = pack2(v, v); }
    for (int i = tid; i < HIDDEN * 3; i += NTHREADS) { float v = W2[i]; w2p[i] = pack2(v, v); }
    if (tid < 3) { float v = b2[tid]; b2p[tid] = pack2(v, v); }
    __syncthreads();

    // ---- init sliding sums for this thread's first element -----------------
    const int base = tid * CHUNK;           // xs index of (t0 - 15)
    float S1 = 0.f, S2 = 0.f, S3 = 0.f, S4 = 0.f;
    #pragma unroll
    for (int k = 0; k < K_WIN; ++k) {
        float v = xs[base + k];
        float v2 = v * v;
        S1 += v; S2 += v2; S3 += v2 * v; S4 += v2 * v2;
    }
    const int t0 = tileStart + base;

    // thread's 48 output floats are contiguous & 16B-aligned: direct float4 STG
    float* __restrict__ othr = out + ((long long)row * T_LEN + t0) * 3;

    // ---- two groups of 8 elements (4 f32x2 pairs each) ---------------------
    #pragma unroll
    for (int g = 0; g < 2; ++g) {
        ull fp0[4], fp1[4], fp2[4], fp3[4], fp4[4], fp5[4];
        #pragma unroll
        for (int pr = 0; pr < 4; ++pr) {
            int j0 = g * GROUP + pr * 2;
            float a0, a1, a2, a3, a4, a5;
            float c0, c1, c2, c3, c4, c5;
            feat_step(xs, base + j0,     t0 + j0,     S1, S2, S3, S4, a0, a1, a2, a3, a4, a5);
            feat_step(xs, base + j0 + 1, t0 + j0 + 1, S1, S2, S3, S4, c0, c1, c2, c3, c4, c5);
            fp0[pr] = pack2(a0, c0);
            fp1[pr] = pack2(a1, c1);
            fp2[pr] = pack2(a2, c2);
            fp3[pr] = pack2(a3, c3);
            fp4[pr] = pack2(a4, c4);
            fp5[pr] = pack2(a5, c5);
        }

        ull acc0[4], acc1[4], acc2[4];
        #pragma unroll
        for (int pr = 0; pr < 4; ++pr) {
            acc0[pr] = b2p[0]; acc1[pr] = b2p[1]; acc2[pr] = b2p[2];
        }

        #pragma unroll 4
        for (int j = 0; j < HIDDEN; ++j) {
            ull w0 = w1t[j * 6 + 0], w1v = w1t[j * 6 + 1], w2v = w1t[j * 6 + 2];
            ull w3 = w1t[j * 6 + 3], w4v = w1t[j * 6 + 4], w5v = w1t[j * 6 + 5];
            ull bj = b1p[j];
            ull v0 = w2p[j * 3 + 0], v1 = w2p[j * 3 + 1], v2 = w2p[j * 3 + 2];
            #pragma unroll
            for (int pr = 0; pr < 4; ++pr) {
                ull h = fma2(fp0[pr], w0, bj);
                h = fma2(fp1[pr], w1v, h);
                h = fma2(fp2[pr], w2v, h);
                h = fma2(fp3[pr], w3, h);
                h = fma2(fp4[pr], w4v, h);
                h = fma2(fp5[pr], w5v, h);
                h = relu2(h);
                acc0[pr] = fma2(h, v0, acc0[pr]);
                acc1[pr] = fma2(h, v1, acc1[pr]);
                acc2[pr] = fma2(h, v2, acc2[pr]);
            }
        }

        // ---- direct register -> gmem writeout: 24 floats = 6 float4 --------
        // f[3*e + k] = logit k of local element e (e = 2*pr + half)
        float f[24];
        #pragma unroll
        for (int pr = 0; pr < 4; ++pr) {
            float lo, hi;
            unpack2(acc0[pr], lo, hi); f[6 * pr + 0] = lo; f[6 * pr + 3] = hi;
            unpack2(acc1[pr], lo, hi); f[6 * pr + 1] = lo; f[6 * pr + 4] = hi;
            unpack2(acc2[pr], lo, hi); f[6 * pr + 2] = lo; f[6 * pr + 5] = hi;
        }
        float4* __restrict__ o4 = reinterpret_cast<float4*>(othr + g * GROUP * 3);
        #pragma unroll
        for (int v = 0; v < 6; ++v) {
            o4[v] = make_float4(f[4 * v], f[4 * v + 1], f[4 * v + 2], f[4 * v + 3]);
        }
    }
}

extern "C" void kernel_launch(void* const* d_in, const int* in_sizes, int n_in,
                              void* d_out, int out_size)
{
    const float* s  = (const float*)d_in[0];   // [B*T]
    const float* W1 = (const float*)d_in[1];   // [6*32]
    const float* b1 = (const float*)d_in[2];   // [32]
    const float* W2 = (const float*)d_in[3];   // [32*3]
    const float* b2 = (const float*)d_in[4];   // [3]
    float* out = (float*)d_out;                // [B*T*3]

    int B = in_sizes[0] / T_LEN;
    dim3 grid(T_LEN / TILE, B);
    gate_router_kernel<<<grid, NTHREADS>>>(s, W1, b1, W2, b2, out);
}